// round 13
// baseline (speedup 1.0000x reference)
#include <cuda_runtime.h>

#define NN 2048
#define FF 64
#define KK 8
#define GROUP 8
#define NGRP (NN / GROUP)     // 256 groups of 8
#define NROUND (NGRP / 2)     // 128 rounds (one group per parity per round)
#define RA 6                  // phase-A rounds (96 ranks per pair)
#define SPAD 2080
#define NBUCK 4096
#define BSHIFT 20
#define BPT (NBUCK / 256)
#define FULLM 0xffffffffu

// Scratch: per-feature bucket-descending (x value, row byte-offset) pairs +
// exact per-group suffix-max stop bounds.
__device__ float2 g_sp[FF * SPAD];
__device__ float  g_bound[FF * NGRP];

__device__ __forceinline__ unsigned key_of(float v) {
    unsigned u = __float_as_uint(v);
    return (u & 0x80000000u) ? ~u : (u | 0x80000000u);
}
__device__ __forceinline__ float val_of(unsigned k) {
    unsigned u = (k & 0x80000000u) ? (k ^ 0x80000000u) : ~k;
    return __uint_as_float(u);
}

// One block per feature f: counting-sort rows into descending-bucket order,
// emit (x value, row byte-offset) + exact suffix-max bounds (shfl scans).
__global__ __launch_bounds__(256) void prep_kernel(const float* __restrict__ x) {
    const int tid = threadIdx.x;
    const int f = blockIdx.x;
    const unsigned lane = tid & 31, wrp = tid >> 5;
    const float NEG_INF = -__int_as_float(0x7f800000);

    __shared__ unsigned skey[NN];
    __shared__ int hist[NBUCK];
    __shared__ float sval[NN];
    __shared__ int wsum[8], wsufs[8];
    __shared__ float wmaxs[8], wsufm[8];
    __shared__ float inclmax[256];

    for (int i = tid; i < NBUCK; i += 256) hist[i] = 0;
    __syncthreads();

    // Pass 1: keys + histogram.
    for (int i = tid; i < NN; i += 256) {
        float v = x[(size_t)i * FF + f];
        unsigned k = key_of(v);
        skey[i] = k;
        atomicAdd(&hist[k >> BSHIFT], 1);
    }
    __syncthreads();

    // Pass 2: descending-exclusive bucket offsets via shfl suffix scan.
    const int base = tid * BPT;
    int csum = 0;
    #pragma unroll
    for (int j = 0; j < BPT; j++) csum += hist[base + j];
    int v = csum;
    #pragma unroll
    for (int d = 1; d < 32; d <<= 1) {
        int o = __shfl_down_sync(FULLM, v, d);
        if (lane + d < 32) v += o;
    }
    if (lane == 0) wsum[wrp] = v;
    __syncthreads();
    if (tid < 8) {
        int w = wsum[tid];
        #pragma unroll
        for (int d = 1; d < 8; d <<= 1) {
            int o = __shfl_down_sync(0xffu, w, d);
            if (tid + d < 8) w += o;
        }
        wsufs[tid] = w;
    }
    __syncthreads();
    int run = (v - csum) + ((wrp < 7) ? wsufs[wrp + 1] : 0);
    #pragma unroll
    for (int j = BPT - 1; j >= 0; j--) {
        int c = hist[base + j];
        hist[base + j] = run;
        run += c;
    }
    __syncthreads();

    // Pass 3: scatter (value, byte offset = idx * NN * 4).
    for (int i = tid; i < NN; i += 256) {
        unsigned k = skey[i];
        float vv = val_of(k);
        int pos = atomicAdd(&hist[k >> BSHIFT], 1);
        g_sp[f * SPAD + pos] = make_float2(vv, __int_as_float(i * (NN * 4)));
        sval[pos] = vv;
    }
    // Pipeline-overrun padding: -inf value, offset 0 (product is -inf or NaN,
    // never inserted).
    for (int i = NN + tid; i < SPAD; i += 256)
        g_sp[f * SPAD + i] = make_float2(NEG_INF, __int_as_float(0));
    __syncthreads();

    // Pass 4: exact suffix-max bound per group of 8.
    float gm = NEG_INF;
    #pragma unroll
    for (int j = 0; j < GROUP; j++) gm = fmaxf(gm, sval[tid * GROUP + j]);
    float vm = gm;
    #pragma unroll
    for (int d = 1; d < 32; d <<= 1) {
        float o = __shfl_down_sync(FULLM, vm, d);
        if (lane + d < 32) vm = fmaxf(vm, o);
    }
    if (lane == 0) wmaxs[wrp] = vm;
    __syncthreads();
    if (tid < 8) {
        float w = wmaxs[tid];
        #pragma unroll
        for (int d = 1; d < 8; d <<= 1) {
            float o = __shfl_down_sync(0xffu, w, d);
            if (tid + d < 8) w = fmaxf(w, o);
        }
        wsufm[tid] = w;
    }
    __syncthreads();
    inclmax[tid] = fmaxf(vm, (wrp < 7) ? wsufm[wrp + 1] : NEG_INF);
    __syncthreads();
    // After group g, remaining products <= max(suffix_max(g+1), 0): adj in [0,1).
    float b = (tid < 255) ? inclmax[tid + 1] : NEG_INF;
    g_bound[f * NGRP + tid] = fmaxf(b, 0.0f);
}

// blockIdx.y = f, blockIdx.x = m-tile of 256. Lane pairs (lane, lane^16)
// share TWO adjacent m (float2 loads): parity 0 scans even groups, parity 1
// odd, own top-8 per m. Per product ~3.5 instr (LDS/addr/LDG.64 amortized).
// Stop: union t7 over pair >= exact suffix bound. Final bitonic pair-merges.
__global__ __launch_bounds__(256) void topk_kernel(const float* __restrict__ x,
                                                   const float* __restrict__ adj,
                                                   float* __restrict__ out) {
    __shared__ float2 s_p[SPAD];
    __shared__ float  s_b[NGRP];
    const int f = blockIdx.y;
    const int tid = threadIdx.x;
    const float NEG_INF = -__int_as_float(0x7f800000);

    #pragma unroll
    for (int i = tid; i < SPAD; i += 256) s_p[i] = g_sp[f * SPAD + i];
    s_b[tid] = g_bound[f * NGRP + tid];
    __syncthreads();

    const int lane = tid & 31, wid = tid >> 5;
    const int pairid = lane & 15, parity = lane >> 4;
    const int m0 = blockIdx.x * 256 + wid * 32 + pairid * 2;
    const char* adjm = (const char*)(adj + m0);

    float ta[KK], tb[KK];
    #pragma unroll
    for (int j = 0; j < KK; j++) { ta[j] = NEG_INF; tb[j] = NEG_INF; }

    float2 ca[GROUP], cb[GROUP];

    // Round r, this parity: products for (m0, m0+1) x group 2r+parity.
    #define LOADC(r, buf)                                                     \
        {   const int gg = 2 * (r) + parity;                                  \
            _Pragma("unroll")                                                 \
            for (int u = 0; u < GROUP; u++) {                                 \
                float2 p = s_p[gg * GROUP + u];                               \
                const float2 a =                                              \
                    *(const float2*)(adjm + __float_as_int(p.y));             \
                buf[u].x = a.x * p.x;                                         \
                buf[u].y = a.y * p.x;                                         \
            }                                                                 \
        }
    #define INSERT(tarr, cval)                                                \
        {   float c = (cval);                                                 \
            if (c > tarr[KK - 1]) {                                           \
                _Pragma("unroll")                                             \
                for (int j = 0; j < KK - 1; j++) {                            \
                    float w = fmaxf(tarr[j], c);                              \
                    c = fminf(tarr[j], c);                                    \
                    tarr[j] = w;                                              \
                }                                                             \
                tarr[KK - 1] = fmaxf(tarr[KK - 1], c);                        \
            }                                                                 \
        }
    #define CONSUME(buf)                                                      \
        {   _Pragma("unroll")                                                 \
            for (int u = 0; u < GROUP; u++) {                                 \
                INSERT(ta, buf[u].x);                                         \
                INSERT(tb, buf[u].y);                                         \
            }                                                                 \
        }

    LOADC(0, ca); LOADC(1, cb);

    // ---- Phase A: rounds 0..RA-1, unconditional, double-buffered. ----
    #pragma unroll
    for (int r = 0; r < RA; r += 2) {
        CONSUME(ca); LOADC(r + 2, ca);
        CONSUME(cb); LOADC(r + 3, cb);
    }

    // ---- Phase B: branchy, exact pair-shared stop bound (both m's done). ----
    float w7 = fminf(ta[KK - 1], tb[KK - 1]);       // weaker of my two lists
    float pw7 = __shfl_xor_sync(FULLM, w7, 16);
    bool done = (fminf(fmaxf(ta[KK - 1], __shfl_xor_sync(FULLM, ta[KK - 1], 16)),
                       fmaxf(tb[KK - 1], __shfl_xor_sync(FULLM, tb[KK - 1], 16)))
                 >= s_b[2 * RA - 1]);
    (void)pw7;
    #pragma unroll 1
    for (int r = RA; r < NROUND; r += 2) {
        if (!__ballot_sync(FULLM, !done)) break;
        if (!done) CONSUME(ca);
        {
            float ua = fmaxf(ta[KK - 1], __shfl_xor_sync(FULLM, ta[KK - 1], 16));
            float ub = fmaxf(tb[KK - 1], __shfl_xor_sync(FULLM, tb[KK - 1], 16));
            if (!done) done = (fminf(ua, ub) >= s_b[2 * r + 1]);
        }
        if (!done) LOADC(r + 2, ca);
        if (!done) CONSUME(cb);
        {
            float ua = fmaxf(ta[KK - 1], __shfl_xor_sync(FULLM, ta[KK - 1], 16));
            float ub = fmaxf(tb[KK - 1], __shfl_xor_sync(FULLM, tb[KK - 1], 16));
            if (!done) done = (fminf(ua, ub) >= s_b[2 * r + 3]);
        }
        if (!done) LOADC(r + 3, cb);
    }

    // ---- Pair merges: union top-8 for each m (bitonic, 3 stages). ----
    #define CSWP(arr, i, jj)                                                  \
        { float hi = fmaxf(arr[i], arr[jj]), lo = fminf(arr[i], arr[jj]);     \
          arr[i] = hi; arr[jj] = lo; }
    float c[KK], d[KK];
    #pragma unroll
    for (int j = 0; j < KK; j++) {
        c[j] = fmaxf(ta[j], __shfl_xor_sync(FULLM, ta[KK - 1 - j], 16));
        d[j] = fmaxf(tb[j], __shfl_xor_sync(FULLM, tb[KK - 1 - j], 16));
    }
    CSWP(c, 0, 4); CSWP(c, 1, 5); CSWP(c, 2, 6); CSWP(c, 3, 7);
    CSWP(c, 0, 2); CSWP(c, 1, 3); CSWP(c, 4, 6); CSWP(c, 5, 7);
    CSWP(c, 0, 1); CSWP(c, 2, 3); CSWP(c, 4, 5); CSWP(c, 6, 7);
    CSWP(d, 0, 4); CSWP(d, 1, 5); CSWP(d, 2, 6); CSWP(d, 3, 7);
    CSWP(d, 0, 2); CSWP(d, 1, 3); CSWP(d, 4, 6); CSWP(d, 5, 7);
    CSWP(d, 0, 1); CSWP(d, 2, 3); CSWP(d, 4, 5); CSWP(d, 6, 7);
    #undef CSWP

    // out[m][j][f]: j=0 is x[m][f], j=1..8 top values desc. Both lanes hold
    // identical c[], d[]; split the stores across the parity pair.
    size_t bse = (size_t)m0 * ((KK + 1) * FF) + f;
    size_t bse1 = bse + (size_t)(KK + 1) * FF;
    if (parity == 0) {
        out[bse]  = x[(size_t)m0 * FF + f];
        out[bse1] = x[(size_t)(m0 + 1) * FF + f];
        #pragma unroll
        for (int j = 0; j < 4; j++) {
            out[bse  + (size_t)(j + 1) * FF] = c[j];
            out[bse1 + (size_t)(j + 1) * FF] = d[j];
        }
    } else {
        #pragma unroll
        for (int j = 4; j < KK; j++) {
            out[bse  + (size_t)(j + 1) * FF] = c[j];
            out[bse1 + (size_t)(j + 1) * FF] = d[j];
        }
    }

    #undef LOADC
    #undef INSERT
    #undef CONSUME
}

extern "C" void kernel_launch(void* const* d_in, const int* in_sizes, int n_in,
                              void* d_out, int out_size) {
    const float* x   = (const float*)d_in[0];
    const float* adj = (const float*)d_in[1];
    if (n_in >= 2 && in_sizes[0] > in_sizes[1]) {  // defensive: x is the smaller input
        const float* t = x; x = adj; adj = t;
    }
    float* out = (float*)d_out;

    prep_kernel<<<FF, 256>>>(x);
    topk_kernel<<<dim3(NN / 256, FF), 256>>>(x, adj, out);
}